// round 11
// baseline (speedup 1.0000x reference)
#include <cuda_runtime.h>
#include <cstdint>

// Problem constants
#define NF 8
#define NK 16
#define NY 16
#define NX 16
#define NP 32
#define NT 8
#define NB 64
#define VOL 65536          // elements per (b,f)

#define AS_STRIDE 68       // 64 cols + 4 pad (conflict-free STS.128 / LDS.32)
#define BT_STRIDE 260      // 256 cols + 4 pad (conflict-free LDS.32 rows)
#define AS_U32    (64*AS_STRIDE)                 // per buffer
#define AS_BYTES  (2*AS_U32*4)                   // 34816 (double buffer)
#define BT_BYTES  (16*BT_STRIDE*4)               // 16640
#define SMEM_TOTAL (AS_BYTES + BT_BYTES)         // 51456 -> 4 CTAs/SM

// Device globals (no allocation allowed)
__device__ float g_klat[NF*NK*NY];
__device__ float g_klon[NF*NK*NX];
__device__ float g_klev[NF*NK*NP];
__device__ float g_r[NF*NK];
__device__ float g_ipart[NF*NK*8];

__device__ __forceinline__ uint32_t f2tf32(float x) {
    uint32_t r; asm("cvt.rna.tf32.f32 %0, %1;" : "=r"(r) : "f"(x)); return r;
}
__device__ __forceinline__ void mma_tf32(float c[4], uint32_t a0, uint32_t a1,
                                         uint32_t a2, uint32_t a3,
                                         uint32_t b0, uint32_t b1) {
    asm volatile(
        "mma.sync.aligned.m16n8k8.row.col.f32.tf32.tf32.f32 "
        "{%0,%1,%2,%3},{%4,%5,%6,%7},{%8,%9},{%0,%1,%2,%3};"
        : "+f"(c[0]), "+f"(c[1]), "+f"(c[2]), "+f"(c[3])
        : "r"(a0), "r"(a1), "r"(a2), "r"(a3), "r"(b0), "r"(b1));
}

// ---------------------------------------------------------------------------
// Prep: 8 sub-CTAs per (f,k) (1024 CTAs). 1D tables + geometric ratio r +
// non-atomic integration partials; zeroes the output buffer.
// ---------------------------------------------------------------------------
__global__ __launch_bounds__(256)
void prep_kernel(const float* __restrict__ qw,
                 const float* __restrict__ mu_lat, const float* __restrict__ ls_lat,
                 const float* __restrict__ mu_lon, const float* __restrict__ ls_lon,
                 const float* __restrict__ mu_lev, const float* __restrict__ ls_lev,
                 const float* __restrict__ lt_time,
                 float* __restrict__ out)
{
    const int bid = blockIdx.x;
    const int fk  = bid >> 3;
    const int sub = bid & 7;
    const int tid = threadIdx.x;
    __shared__ float s_lat[NY], s_lon[NX], s_lev[NP];
    __shared__ float s_part[8];

    if (tid < 8) out[bid*8 + tid] = 0.f;   // zero out (1024*8 = 8192)

    if (tid < NY) {
        float c = -1.f + 2.f * (float)tid / (float)(NY - 1);
        float z = (c - mu_lat[fk]) / expf(ls_lat[fk]);
        float v = expf(-0.5f * z * z);
        s_lat[tid] = v;
        if (sub == 0) g_klat[fk*NY + tid] = v;
    } else if (tid < 32) {
        int x = tid - 16;
        float c = -1.f + 2.f * (float)x / (float)(NX - 1);
        float z = (c - mu_lon[fk]) / expf(ls_lon[fk]);
        float v = expf(-0.5f * z * z);
        s_lon[x] = v;
        if (sub == 0) g_klon[fk*NX + x] = v;
    } else if (tid < 64) {
        int p = tid - 32;
        float c = -1.f + 2.f * (float)p / (float)(NP - 1);
        float z = (c - mu_lev[fk]) / expf(ls_lev[fk]);
        float v = expf(-0.5f * z * z);
        s_lev[p] = v;
        if (sub == 0) g_klev[fk*NP + p] = v;
    }
    float tau = expf(lt_time[fk]) + 1e-6f;
    float r = expf(-1.f / tau);
    if (sub == 0 && tid == 0) g_r[fk] = r;
    __syncthreads();

    const float4* q4 = (const float4*)qw;
    float local = 0.f;
    #pragma unroll
    for (int it = 0; it < 4; ++it) {
        int idx = sub*1024 + it*256 + tid;
        float4 q0 = q4[idx*2];
        float4 q1 = q4[idx*2 + 1];
        float s = q1.w;
        s = fmaf(s, r, q1.z); s = fmaf(s, r, q1.y); s = fmaf(s, r, q1.x);
        s = fmaf(s, r, q0.w); s = fmaf(s, r, q0.z); s = fmaf(s, r, q0.y);
        s = fmaf(s, r, q0.x);
        int p = idx & 31, x = (idx >> 5) & 15, y = idx >> 9;
        local += s * (s_lat[y] * s_lon[x] * s_lev[p]);
    }
    #pragma unroll
    for (int o = 16; o; o >>= 1) local += __shfl_xor_sync(0xffffffffu, local, o);
    if ((tid & 31) == 0) s_part[tid >> 5] = local;
    __syncthreads();
    if (tid == 0) {
        float s = 0.f;
        #pragma unroll
        for (int w = 0; w < 8; ++w) s += s_part[w];
        g_ipart[bid] = s;
    }
}

// ---------------------------------------------------------------------------
// Main GEMM kernel: grid = 2048 (f = bid&7, sl = bid>>3 = one yx slice).
// C[64,16] = patch[64, 256] x W[256, 16] (tf32 mma.sync m16n8k8).
// Register double buffering over 4 rounds of 64 cols; B stored TRANSPOSED
// (Bt[k][i], row-pattern frag loads) -> 51.5 KB smem, 4 CTAs/SM.
// s_par (epilogue scratch) aliases As buffer 0 (dead by then).
// Epilogue: pair-reduce K-halves via smem, atomicAdd into out.
// ---------------------------------------------------------------------------
__global__ __launch_bounds__(256, 4)
void feat_kernel(const float* __restrict__ patch, const float* __restrict__ qw,
                 float* __restrict__ out)
{
    extern __shared__ __align__(16) char dynsmem[];
    uint32_t* As    = (uint32_t*)dynsmem;                      // [2][64][68]
    uint32_t* Bt    = (uint32_t*)(dynsmem + AS_BYTES);         // [16][260]
    float*    s_par = (float*)dynsmem;                         // alias As buf0
    __shared__ float s_cl[16];

    const int bid  = blockIdx.x;
    const int f    = bid & 7;
    const int sl   = bid >> 3;            // yx index 0..255
    const int tid  = threadIdx.x;
    const int lane = tid & 31, wid = tid >> 5;
    const int g = lane >> 2, tg = lane & 3;
    const int mt = wid & 3, kh = wid >> 2;

    if (tid < 16) {
        const int fk = f*16 + tid;
        float integ = 0.f;
        #pragma unroll
        for (int i = 0; i < 8; ++i) integ += g_ipart[fk*8 + i];
        s_cl[tid] = g_klat[fk*NY + (sl >> 4)] * g_klon[fk*NX + (sl & 15)]
                    / (integ + 1e-4f);
    }
    __syncthreads();

    // Build Bt: W[i=tid][k] = qw_i * klev*r^t * (klat*klon/integ), transposed
    {
        const int p = (tid >> 3) & 31, t = tid & 7;
        const float qwv = qw[sl*256 + tid];
        #pragma unroll
        for (int k = 0; k < 16; ++k) {
            const float r = g_r[f*16 + k];
            const float r2 = r*r, r4 = r2*r2;
            float rt = 1.f;
            if (t & 1) rt *= r;
            if (t & 2) rt *= r2;
            if (t & 4) rt *= r4;
            const float kl = g_klev[(f*16 + k)*NP + p];
            Bt[k*BT_STRIDE + tid] = f2tf32(qwv * kl * rt * s_cl[k]);
        }
    }

    const size_t bstride = (size_t)NF * VOL;
    const float* abase = patch + (size_t)f * VOL + (size_t)sl * 256;
    const int row0 = tid >> 4;            // rows row0, +16, +32, +48
    const int c4   = tid & 15;

    // Round 0 loads + store into buffer 0
    float4 rbuf[4];
    #pragma unroll
    for (int it = 0; it < 4; ++it)
        rbuf[it] = *(const float4*)(abase + (size_t)(row0 + it*16) * bstride + c4*4);
    #pragma unroll
    for (int it = 0; it < 4; ++it) {
        uint4 w;
        w.x = f2tf32(rbuf[it].x); w.y = f2tf32(rbuf[it].y);
        w.z = f2tf32(rbuf[it].z); w.w = f2tf32(rbuf[it].w);
        *(uint4*)&As[(row0 + it*16)*AS_STRIDE + c4*4] = w;
    }
    __syncthreads();

    float acc[2][4] = {};
    #pragma unroll
    for (int sub = 0; sub < 4; ++sub) {
        // Issue next round's loads early (overlap with MMA below)
        if (sub < 3) {
            #pragma unroll
            for (int it = 0; it < 4; ++it)
                rbuf[it] = *(const float4*)(abase + (size_t)(row0 + it*16) * bstride
                                            + (sub + 1)*64 + c4*4);
        }

        // MMA on current buffer: warp (mt, kh); kh covers 4 of 8 k-tiles
        const uint32_t* Ab = As + (sub & 1)*AS_U32;
        #pragma unroll
        for (int j = 0; j < 4; ++j) {
            const int icl = kh*32 + j*8;       // col within 64-col round
            const int icb = sub*64 + icl;      // col in Bt (0..255)
            const uint32_t a0 = Ab[(mt*16 + g    )*AS_STRIDE + icl + tg];
            const uint32_t a1 = Ab[(mt*16 + g + 8)*AS_STRIDE + icl + tg];
            const uint32_t a2 = Ab[(mt*16 + g    )*AS_STRIDE + icl + tg + 4];
            const uint32_t a3 = Ab[(mt*16 + g + 8)*AS_STRIDE + icl + tg + 4];
            const uint32_t b0 = Bt[(g    )*BT_STRIDE + icb + tg];
            const uint32_t b1 = Bt[(g    )*BT_STRIDE + icb + tg + 4];
            const uint32_t c0 = Bt[(g + 8)*BT_STRIDE + icb + tg];
            const uint32_t c1 = Bt[(g + 8)*BT_STRIDE + icb + tg + 4];
            mma_tf32(acc[0], a0, a1, a2, a3, b0, b1);
            mma_tf32(acc[1], a0, a1, a2, a3, c0, c1);
        }

        // Store next round into the other buffer, then one barrier
        if (sub < 3) {
            uint32_t* An = As + ((sub + 1) & 1)*AS_U32;
            #pragma unroll
            for (int it = 0; it < 4; ++it) {
                uint4 w;
                w.x = f2tf32(rbuf[it].x); w.y = f2tf32(rbuf[it].y);
                w.z = f2tf32(rbuf[it].z); w.w = f2tf32(rbuf[it].w);
                *(uint4*)&An[(row0 + it*16)*AS_STRIDE + c4*4] = w;
            }
            __syncthreads();
        }
    }

    // Pair-reduce the two K-halves (s_par aliases As buf0 — dead since the
    // sub2->3 barrier), then atomicAdd into out.
    __syncthreads();
    if (kh == 1) {
        float* sp = s_par + mt*256;
        sp[(g    )*16 + tg*2    ] = acc[0][0];
        sp[(g    )*16 + tg*2 + 1] = acc[0][1];
        sp[(g + 8)*16 + tg*2    ] = acc[0][2];
        sp[(g + 8)*16 + tg*2 + 1] = acc[0][3];
        sp[(g    )*16 + 8 + tg*2    ] = acc[1][0];
        sp[(g    )*16 + 8 + tg*2 + 1] = acc[1][1];
        sp[(g + 8)*16 + 8 + tg*2    ] = acc[1][2];
        sp[(g + 8)*16 + 8 + tg*2 + 1] = acc[1][3];
    }
    __syncthreads();
    if (kh == 0) {
        const float* sp = s_par + mt*256;
        const int r0 = mt*16 + g, r1 = r0 + 8;
        float* o0 = out + (size_t)r0 * (NF*NK) + f*NK;
        float* o1 = out + (size_t)r1 * (NF*NK) + f*NK;
        atomicAdd(&o0[tg*2    ], acc[0][0] + sp[(g    )*16 + tg*2    ]);
        atomicAdd(&o0[tg*2 + 1], acc[0][1] + sp[(g    )*16 + tg*2 + 1]);
        atomicAdd(&o1[tg*2    ], acc[0][2] + sp[(g + 8)*16 + tg*2    ]);
        atomicAdd(&o1[tg*2 + 1], acc[0][3] + sp[(g + 8)*16 + tg*2 + 1]);
        atomicAdd(&o0[8 + tg*2    ], acc[1][0] + sp[(g    )*16 + 8 + tg*2    ]);
        atomicAdd(&o0[8 + tg*2 + 1], acc[1][1] + sp[(g    )*16 + 8 + tg*2 + 1]);
        atomicAdd(&o1[8 + tg*2    ], acc[1][2] + sp[(g + 8)*16 + 8 + tg*2    ]);
        atomicAdd(&o1[8 + tg*2 + 1], acc[1][3] + sp[(g + 8)*16 + 8 + tg*2 + 1]);
    }
}

// ---------------------------------------------------------------------------
// Launch. Inputs (metadata order): patch, quadweights, mu_lat, logsigma_lat,
// mu_lon, logsigma_lon, mu_lev, logsigma_lev, logtau_time.
// ---------------------------------------------------------------------------
extern "C" void kernel_launch(void* const* d_in, const int* in_sizes, int n_in,
                              void* d_out, int out_size)
{
    (void)in_sizes; (void)n_in; (void)out_size;
    const float* patch  = (const float*)d_in[0];
    const float* qw     = (const float*)d_in[1];
    const float* mu_lat = (const float*)d_in[2];
    const float* ls_lat = (const float*)d_in[3];
    const float* mu_lon = (const float*)d_in[4];
    const float* ls_lon = (const float*)d_in[5];
    const float* mu_lev = (const float*)d_in[6];
    const float* ls_lev = (const float*)d_in[7];
    const float* lt     = (const float*)d_in[8];
    float* out = (float*)d_out;

    static bool attr_set = false;
    if (!attr_set) {
        cudaFuncSetAttribute(feat_kernel,
                             cudaFuncAttributeMaxDynamicSharedMemorySize, SMEM_TOTAL);
        attr_set = true;
    }

    prep_kernel<<<NF*NK*8, 256>>>(qw, mu_lat, ls_lat, mu_lon, ls_lon,
                                  mu_lev, ls_lev, lt, out);
    feat_kernel<<<2048, 256, SMEM_TOTAL>>>(patch, qw, out);
}

// round 12
// speedup vs baseline: 1.1293x; 1.1293x over previous
#include <cuda_runtime.h>
#include <cstdint>

// Problem constants
#define NF 8
#define NK 16
#define NY 16
#define NX 16
#define NP 32
#define NT 8
#define NB 64
#define VOL 65536          // elements per (b,f)

#define AS_STRIDE 68       // 64 cols + 4 pad (conflict-free writes / LDS.32)
#define BS_STRIDE 24       // 16 cols + 8 pad (conflict-free b-frag LDS.32)
#define AS_U32    (64*AS_STRIDE)                 // per buffer (fp32 words)
#define AS_BYTES  (2*AS_U32*4)                   // 34816 (double buffer)
#define BS_BYTES  (256*BS_STRIDE*4)              // 24576
#define SP_BYTES  (4*16*16*4)                    // 4096
#define SMEM_TOTAL (AS_BYTES + BS_BYTES + SP_BYTES)   // 63488 -> 3 CTAs/SM

// Device globals (no allocation allowed)
__device__ float g_klat[NF*NK*NY];
__device__ float g_klon[NF*NK*NX];
__device__ float g_klev[NF*NK*NP];
__device__ float g_r[NF*NK];
__device__ float g_ipart[NF*NK*8];

__device__ __forceinline__ uint32_t f2tf32(float x) {
    uint32_t r; asm("cvt.rna.tf32.f32 %0, %1;" : "=r"(r) : "f"(x)); return r;
}
__device__ __forceinline__ void mma_tf32(float c[4], uint32_t a0, uint32_t a1,
                                         uint32_t a2, uint32_t a3,
                                         uint32_t b0, uint32_t b1) {
    asm volatile(
        "mma.sync.aligned.m16n8k8.row.col.f32.tf32.tf32.f32 "
        "{%0,%1,%2,%3},{%4,%5,%6,%7},{%8,%9},{%0,%1,%2,%3};"
        : "+f"(c[0]), "+f"(c[1]), "+f"(c[2]), "+f"(c[3])
        : "r"(a0), "r"(a1), "r"(a2), "r"(a3), "r"(b0), "r"(b1));
}

// cp.async helpers (16B, default .ca path)
__device__ __forceinline__ void cp16(void* dst_smem, const void* src) {
    uint32_t d = (uint32_t)__cvta_generic_to_shared(dst_smem);
    asm volatile("cp.async.ca.shared.global [%0],[%1],16;" :: "r"(d), "l"(src));
}
__device__ __forceinline__ void cp_commit() {
    asm volatile("cp.async.commit_group;");
}
template<int N> __device__ __forceinline__ void cp_wait() {
    asm volatile("cp.async.wait_group %0;" :: "n"(N));
}

// ---------------------------------------------------------------------------
// Prep: 8 sub-CTAs per (f,k) (1024 CTAs). 1D tables + geometric ratio r +
// non-atomic integration partials; zeroes the output buffer.
// ---------------------------------------------------------------------------
__global__ __launch_bounds__(256)
void prep_kernel(const float* __restrict__ qw,
                 const float* __restrict__ mu_lat, const float* __restrict__ ls_lat,
                 const float* __restrict__ mu_lon, const float* __restrict__ ls_lon,
                 const float* __restrict__ mu_lev, const float* __restrict__ ls_lev,
                 const float* __restrict__ lt_time,
                 float* __restrict__ out)
{
    const int bid = blockIdx.x;
    const int fk  = bid >> 3;
    const int sub = bid & 7;
    const int tid = threadIdx.x;
    __shared__ float s_lat[NY], s_lon[NX], s_lev[NP];
    __shared__ float s_part[8];

    if (tid < 8) out[bid*8 + tid] = 0.f;   // zero out (1024*8 = 8192)

    if (tid < NY) {
        float c = -1.f + 2.f * (float)tid / (float)(NY - 1);
        float z = (c - mu_lat[fk]) / expf(ls_lat[fk]);
        float v = expf(-0.5f * z * z);
        s_lat[tid] = v;
        if (sub == 0) g_klat[fk*NY + tid] = v;
    } else if (tid < 32) {
        int x = tid - 16;
        float c = -1.f + 2.f * (float)x / (float)(NX - 1);
        float z = (c - mu_lon[fk]) / expf(ls_lon[fk]);
        float v = expf(-0.5f * z * z);
        s_lon[x] = v;
        if (sub == 0) g_klon[fk*NX + x] = v;
    } else if (tid < 64) {
        int p = tid - 32;
        float c = -1.f + 2.f * (float)p / (float)(NP - 1);
        float z = (c - mu_lev[fk]) / expf(ls_lev[fk]);
        float v = expf(-0.5f * z * z);
        s_lev[p] = v;
        if (sub == 0) g_klev[fk*NP + p] = v;
    }
    float tau = expf(lt_time[fk]) + 1e-6f;
    float r = expf(-1.f / tau);
    if (sub == 0 && tid == 0) g_r[fk] = r;
    __syncthreads();

    const float4* q4 = (const float4*)qw;
    float local = 0.f;
    #pragma unroll
    for (int it = 0; it < 4; ++it) {
        int idx = sub*1024 + it*256 + tid;
        float4 q0 = q4[idx*2];
        float4 q1 = q4[idx*2 + 1];
        float s = q1.w;
        s = fmaf(s, r, q1.z); s = fmaf(s, r, q1.y); s = fmaf(s, r, q1.x);
        s = fmaf(s, r, q0.w); s = fmaf(s, r, q0.z); s = fmaf(s, r, q0.y);
        s = fmaf(s, r, q0.x);
        int p = idx & 31, x = (idx >> 5) & 15, y = idx >> 9;
        local += s * (s_lat[y] * s_lon[x] * s_lev[p]);
    }
    #pragma unroll
    for (int o = 16; o; o >>= 1) local += __shfl_xor_sync(0xffffffffu, local, o);
    if ((tid & 31) == 0) s_part[tid >> 5] = local;
    __syncthreads();
    if (tid == 0) {
        float s = 0.f;
        #pragma unroll
        for (int w = 0; w < 8; ++w) s += s_part[w];
        g_ipart[bid] = s;
    }
}

// ---------------------------------------------------------------------------
// Main GEMM kernel: grid = 2048 (f = bid&7, sl = bid>>3 = one yx slice).
// C[64,16] = patch[64, 256] x W[256, 16] (tf32 mma.sync m16n8k8).
// A staged via cp.async double buffer (raw fp32, commit-per-stage,
// wait_group<1> + CTA barrier): no STS pass, no staging registers, LSU runs
// a full round ahead of the MMA loop. Fragments cvt.rna'd to tf32 at load.
// W built in smem from the 1D tables (zero DRAM cost).
// Epilogue: pair-reduce K-halves via smem, atomicAdd into out.
// ---------------------------------------------------------------------------
__global__ __launch_bounds__(256, 3)
void feat_kernel(const float* __restrict__ patch, const float* __restrict__ qw,
                 float* __restrict__ out)
{
    extern __shared__ __align__(16) char dynsmem[];
    float*    As    = (float*)dynsmem;                         // [2][64][68] fp32
    uint32_t* Bs    = (uint32_t*)(dynsmem + AS_BYTES);         // [256][24] tf32
    float*    s_par = (float*)(dynsmem + AS_BYTES + BS_BYTES); // [4][16][16]
    __shared__ float s_cl[16];

    const int bid  = blockIdx.x;
    const int f    = bid & 7;
    const int sl   = bid >> 3;            // yx index 0..255
    const int tid  = threadIdx.x;
    const int lane = tid & 31, wid = tid >> 5;
    const int g = lane >> 2, tg = lane & 3;
    const int mt = wid & 3, kh = wid >> 2;

    const size_t bstride = (size_t)NF * VOL;
    const float* abase = patch + (size_t)f * VOL + (size_t)sl * 256;
    const int row0 = tid >> 4;            // rows row0, +16, +32, +48
    const int c4   = tid & 15;

    // Kick off stage 0 copies immediately (overlap with table build)
    #pragma unroll
    for (int it = 0; it < 4; ++it)
        cp16(&As[(row0 + it*16)*AS_STRIDE + c4*4],
             abase + (size_t)(row0 + it*16) * bstride + c4*4);
    cp_commit();

    if (tid < 16) {
        const int fk = f*16 + tid;
        float integ = 0.f;
        #pragma unroll
        for (int i = 0; i < 8; ++i) integ += g_ipart[fk*8 + i];
        s_cl[tid] = g_klat[fk*NY + (sl >> 4)] * g_klon[fk*NX + (sl & 15)]
                    / (integ + 1e-4f);
    }
    __syncthreads();

    // Build B: W[i][k] = qw_i * klev*r^t * (klat*klon/integ), tf32
    {
        const int p = (tid >> 3) & 31, t = tid & 7;
        const float qwv = qw[sl*256 + tid];
        #pragma unroll
        for (int kq = 0; kq < 4; ++kq) {
            uint4 pk;
            uint32_t* pe = (uint32_t*)&pk;
            #pragma unroll
            for (int e = 0; e < 4; ++e) {
                const int k = kq*4 + e;
                const float r = g_r[f*16 + k];
                const float r2 = r*r, r4 = r2*r2;
                float rt = 1.f;
                if (t & 1) rt *= r;
                if (t & 2) rt *= r2;
                if (t & 4) rt *= r4;
                const float kl = g_klev[(f*16 + k)*NP + p];
                pe[e] = f2tf32(qwv * kl * rt * s_cl[k]);
            }
            *(uint4*)&Bs[tid*BS_STRIDE + kq*4] = pk;
        }
    }

    // Stage 1 copies into buffer 1
    #pragma unroll
    for (int it = 0; it < 4; ++it)
        cp16(&As[AS_U32 + (row0 + it*16)*AS_STRIDE + c4*4],
             abase + (size_t)(row0 + it*16) * bstride + 64 + c4*4);
    cp_commit();

    float acc[2][4] = {};
    #pragma unroll
    for (int sub = 0; sub < 4; ++sub) {
        // Wait for stage `sub` (all but the newest group), then CTA barrier
        if (sub < 3) cp_wait<1>(); else cp_wait<0>();
        __syncthreads();

        // MMA on buffer sub&1: warp (mt, kh); kh covers 4 of 8 k-tiles
        const float* Ab = As + (sub & 1)*AS_U32;
        const float* ar0 = Ab + (mt*16 + g    )*AS_STRIDE;
        const float* ar8 = Ab + (mt*16 + g + 8)*AS_STRIDE;
        #pragma unroll
        for (int j = 0; j < 4; ++j) {
            const int icl = kh*32 + j*8;       // col within 64-col round
            const int icb = sub*64 + icl;      // row in Bs (0..255)
            const uint32_t a0 = f2tf32(ar0[icl + tg]);
            const uint32_t a1 = f2tf32(ar8[icl + tg]);
            const uint32_t a2 = f2tf32(ar0[icl + tg + 4]);
            const uint32_t a3 = f2tf32(ar8[icl + tg + 4]);
            const uint32_t b0 = Bs[(icb + tg    )*BS_STRIDE + g];
            const uint32_t b1 = Bs[(icb + tg + 4)*BS_STRIDE + g];
            const uint32_t c0 = Bs[(icb + tg    )*BS_STRIDE + g + 8];
            const uint32_t c1 = Bs[(icb + tg + 4)*BS_STRIDE + g + 8];
            mma_tf32(acc[0], a0, a1, a2, a3, b0, b1);
            mma_tf32(acc[1], a0, a1, a2, a3, c0, c1);
        }
        __syncthreads();   // buffer sub&1 fully consumed

        // Issue stage sub+2 into the just-freed buffer
        if (sub < 2) {
            const int col0 = (sub + 2)*64;
            #pragma unroll
            for (int it = 0; it < 4; ++it)
                cp16(&As[(sub & 1)*AS_U32 + (row0 + it*16)*AS_STRIDE + c4*4],
                     abase + (size_t)(row0 + it*16) * bstride + col0 + c4*4);
            cp_commit();
        }
    }

    // Pair-reduce the two K-halves, then atomicAdd into out.
    if (kh == 1) {
        float* sp = s_par + mt*256;
        sp[(g    )*16 + tg*2    ] = acc[0][0];
        sp[(g    )*16 + tg*2 + 1] = acc[0][1];
        sp[(g + 8)*16 + tg*2    ] = acc[0][2];
        sp[(g + 8)*16 + tg*2 + 1] = acc[0][3];
        sp[(g    )*16 + 8 + tg*2    ] = acc[1][0];
        sp[(g    )*16 + 8 + tg*2 + 1] = acc[1][1];
        sp[(g + 8)*16 + 8 + tg*2    ] = acc[1][2];
        sp[(g + 8)*16 + 8 + tg*2 + 1] = acc[1][3];
    }
    __syncthreads();
    if (kh == 0) {
        const float* sp = s_par + mt*256;
        const int r0 = mt*16 + g, r1 = r0 + 8;
        float* o0 = out + (size_t)r0 * (NF*NK) + f*NK;
        float* o1 = out + (size_t)r1 * (NF*NK) + f*NK;
        atomicAdd(&o0[tg*2    ], acc[0][0] + sp[(g    )*16 + tg*2    ]);
        atomicAdd(&o0[tg*2 + 1], acc[0][1] + sp[(g    )*16 + tg*2 + 1]);
        atomicAdd(&o1[tg*2    ], acc[0][2] + sp[(g + 8)*16 + tg*2    ]);
        atomicAdd(&o1[tg*2 + 1], acc[0][3] + sp[(g + 8)*16 + tg*2 + 1]);
        atomicAdd(&o0[8 + tg*2    ], acc[1][0] + sp[(g    )*16 + 8 + tg*2    ]);
        atomicAdd(&o0[8 + tg*2 + 1], acc[1][1] + sp[(g    )*16 + 8 + tg*2 + 1]);
        atomicAdd(&o1[8 + tg*2    ], acc[1][2] + sp[(g + 8)*16 + 8 + tg*2    ]);
        atomicAdd(&o1[8 + tg*2 + 1], acc[1][3] + sp[(g + 8)*16 + 8 + tg*2 + 1]);
    }
}

// ---------------------------------------------------------------------------
// Launch. Inputs (metadata order): patch, quadweights, mu_lat, logsigma_lat,
// mu_lon, logsigma_lon, mu_lev, logsigma_lev, logtau_time.
// ---------------------------------------------------------------------------
extern "C" void kernel_launch(void* const* d_in, const int* in_sizes, int n_in,
                              void* d_out, int out_size)
{
    (void)in_sizes; (void)n_in; (void)out_size;
    const float* patch  = (const float*)d_in[0];
    const float* qw     = (const float*)d_in[1];
    const float* mu_lat = (const float*)d_in[2];
    const float* ls_lat = (const float*)d_in[3];
    const float* mu_lon = (const float*)d_in[4];
    const float* ls_lon = (const float*)d_in[5];
    const float* mu_lev = (const float*)d_in[6];
    const float* ls_lev = (const float*)d_in[7];
    const float* lt     = (const float*)d_in[8];
    float* out = (float*)d_out;

    static bool attr_set = false;
    if (!attr_set) {
        cudaFuncSetAttribute(feat_kernel,
                             cudaFuncAttributeMaxDynamicSharedMemorySize, SMEM_TOTAL);
        attr_set = true;
    }

    prep_kernel<<<NF*NK*8, 256>>>(qw, mu_lat, ls_lat, mu_lon, ls_lon,
                                  mu_lev, ls_lev, lt, out);
    feat_kernel<<<2048, 256, SMEM_TOTAL>>>(patch, qw, out);
}